// round 1
// baseline (speedup 1.0000x reference)
#include <cuda_runtime.h>
#include <cuda_bf16.h>
#include <math.h>

#define D_MODEL 768
#define N_HEADS 12
#define HEAD_DIM 64
#define FFN_DIM 3072
#define T_TOK 2048          // C*S = 16*128 tokens per batch
#define BATCH 2
#define M_ROWS (BATCH * T_TOK)   // 4096

// -------------------- scratch (static device globals; no allocs) ----------
__device__ float g_ni[M_ROWS * D_MODEL];
__device__ float g_q[M_ROWS * D_MODEL];
__device__ float g_k[M_ROWS * D_MODEL];
__device__ float g_v[M_ROWS * D_MODEL];
__device__ float g_attn[M_ROWS * D_MODEL];
__device__ float g_res1[M_ROWS * D_MODEL];
__device__ float g_ffin[M_ROWS * D_MODEL];
__device__ float g_h[M_ROWS * FFN_DIM];

// -------------------- block reduction helper ------------------------------
__device__ __forceinline__ float block_sum_256(float val) {
    __shared__ float red[8];
    int lane = threadIdx.x & 31, w = threadIdx.x >> 5;
#pragma unroll
    for (int o = 16; o; o >>= 1) val += __shfl_xor_sync(0xffffffffu, val, o);
    if (lane == 0) red[w] = val;
    __syncthreads();
    if (w == 0) {
        float t = (lane < 8) ? red[lane] : 0.f;
#pragma unroll
        for (int o = 4; o; o >>= 1) t += __shfl_xor_sync(0xffffffffu, t, o);
        if (lane == 0) red[0] = t;
    }
    __syncthreads();
    float r = red[0];
    __syncthreads();
    return r;
}

// -------------------- LayerNorm: one block per row (768 cols) -------------
__global__ void ln_kernel(const float* __restrict__ x, const float* __restrict__ g,
                          const float* __restrict__ bta, float* __restrict__ y) {
    size_t row = blockIdx.x;
    int tid = threadIdx.x;
    const float* xr = x + row * D_MODEL;
    float v0 = xr[tid], v1 = xr[tid + 256], v2 = xr[tid + 512];
    float mu = block_sum_256(v0 + v1 + v2) * (1.f / 768.f);
    float d0 = v0 - mu, d1 = v1 - mu, d2 = v2 - mu;
    float var = block_sum_256(d0 * d0 + d1 * d1 + d2 * d2) * (1.f / 768.f);
    float rs = rsqrtf(var + 1e-5f);
    float* yr = y + row * D_MODEL;
    yr[tid]       = d0 * rs * g[tid]       + bta[tid];
    yr[tid + 256] = d1 * rs * g[tid + 256] + bta[tid + 256];
    yr[tid + 512] = d2 * rs * g[tid + 512] + bta[tid + 512];
}

// -------------------- generic 64x64 tiled fp32 GEMM -----------------------
// C[M,N] = epilogue( alpha * (A[M,K] @ B[K,N] + bias[N]) )  (+ res[M,N])
template <bool GELU>
__global__ void gemm64(const float* __restrict__ A, const float* __restrict__ Bm,
                       const float* __restrict__ bias, const float* __restrict__ res,
                       float* __restrict__ C, int M, int N, int K, float alpha) {
    __shared__ float As[16][64];
    __shared__ float Bs[16][64];
    int tid = threadIdx.x;
    int brow = blockIdx.y * 64, bcol = blockIdx.x * 64;
    int ty = tid >> 4, tx = tid & 15;

    int arow = tid >> 2, ac4 = (tid & 3) * 4;       // A tile: 64 rows x 16 cols
    int brl  = tid >> 4, bc4 = (tid & 15) * 4;      // B tile: 16 rows x 64 cols
    const float* Aptr = A + (size_t)(brow + arow) * K + ac4;
    const float* Bptr = Bm + (size_t)brl * N + bcol + bc4;

    float acc[4][4] = {};
    for (int k0 = 0; k0 < K; k0 += 16) {
        float4 av = *(const float4*)(Aptr + k0);
        As[ac4 + 0][arow] = av.x;
        As[ac4 + 1][arow] = av.y;
        As[ac4 + 2][arow] = av.z;
        As[ac4 + 3][arow] = av.w;
        float4 bv = *(const float4*)(Bptr + (size_t)k0 * N);
        *(float4*)&Bs[brl][bc4] = bv;
        __syncthreads();
#pragma unroll
        for (int kk = 0; kk < 16; kk++) {
            float4 a = *(const float4*)&As[kk][ty * 4];
            float4 b = *(const float4*)&Bs[kk][tx * 4];
            acc[0][0] += a.x * b.x; acc[0][1] += a.x * b.y; acc[0][2] += a.x * b.z; acc[0][3] += a.x * b.w;
            acc[1][0] += a.y * b.x; acc[1][1] += a.y * b.y; acc[1][2] += a.y * b.z; acc[1][3] += a.y * b.w;
            acc[2][0] += a.z * b.x; acc[2][1] += a.z * b.y; acc[2][2] += a.z * b.z; acc[2][3] += a.z * b.w;
            acc[3][0] += a.w * b.x; acc[3][1] += a.w * b.y; acc[3][2] += a.w * b.z; acc[3][3] += a.w * b.w;
        }
        __syncthreads();
    }

    int row0 = brow + ty * 4, col0 = bcol + tx * 4;
    float bb[4];
#pragma unroll
    for (int j = 0; j < 4; j++) bb[j] = bias[col0 + j];
#pragma unroll
    for (int i = 0; i < 4; i++) {
        float out[4];
#pragma unroll
        for (int j = 0; j < 4; j++) {
            float v = alpha * (acc[i][j] + bb[j]);
            if (GELU) v = v * normcdff(v);
            out[j] = v;
        }
        if (res) {
            const float* rr = res + (size_t)(row0 + i) * N + col0;
#pragma unroll
            for (int j = 0; j < 4; j++) out[j] += rr[j];
        }
        float4 o4 = make_float4(out[0], out[1], out[2], out[3]);
        *(float4*)(C + (size_t)(row0 + i) * N + col0) = o4;
    }
}

// -------------------- p-RoPE in-place on q and k --------------------------
// only first 16 of 32 frequency bands rotate (rope_percent=0.5)
__global__ void rope_kernel(float* __restrict__ q, float* __restrict__ k) {
    int idx = blockIdx.x * blockDim.x + threadIdx.x;
    const int total = BATCH * T_TOK * N_HEADS * 16;
    if (idx >= total) return;
    int i = idx & 15;
    int h = (idx >> 4) % N_HEADS;
    int t = (idx / (16 * N_HEADS)) % T_TOK;
    int b = idx / (16 * N_HEADS * T_TOK);
    size_t base = ((size_t)(b * T_TOK + t)) * D_MODEL + h * HEAD_DIM + i;
    double ts = pow(10000.0, (double)i / 32.0);
    double ang = (double)t / ts;
    double sd, cd;
    sincos(ang, &sd, &cd);
    float sf = (float)sd, cf = (float)cd;
    float x1 = q[base], x2 = q[base + 32];
    q[base]      = x1 * cf - x2 * sf;
    q[base + 32] = x2 * cf + x1 * sf;
    x1 = k[base]; x2 = k[base + 32];
    k[base]      = x1 * cf - x2 * sf;
    k[base + 32] = x2 * cf + x1 * sf;
}

// -------------------- flash attention -------------------------------------
// grid: (T/64, H, B), 256 threads. q,k,v in [B,T,H*hd] layout (strided rows).
// smem: QsT[64][64] d-major | KsT[64][64] d-major | Vs[64][64] row-major |
//       Sc[64][65] | m[64] l[64] scale[64]
#define ATTN_SMEM_FLOATS (4096 * 3 + 64 * 65 + 192)

__global__ void attn_kernel(const float* __restrict__ Q, const float* __restrict__ Kk,
                            const float* __restrict__ V, const float* __restrict__ ab,
                            float* __restrict__ O) {
    extern __shared__ float sm[];
    float* QsT = sm;
    float* KsT = sm + 4096;
    float* Vs  = sm + 8192;
    float* Sc  = sm + 12288;
    float* mrow = Sc + 64 * 65;
    float* lrow = mrow + 64;
    float* srow = lrow + 64;

    int tid = threadIdx.x;
    int qb = blockIdx.x * 64;
    int h = blockIdx.y, b = blockIdx.z;
    size_t bh = (size_t)b * T_TOK * D_MODEL + h * HEAD_DIM;
    const float* qp = Q + bh;
    const float* kp = Kk + bh;
    const float* vp = V + bh;

    // load Q tile transposed (d-major)
#pragma unroll
    for (int it = 0; it < 4; it++) {
        int idx = tid + it * 256;
        int r = idx >> 4, c4 = (idx & 15) * 4;
        float4 val = *(const float4*)(qp + (size_t)(qb + r) * D_MODEL + c4);
        QsT[(c4 + 0) * 64 + r] = val.x;
        QsT[(c4 + 1) * 64 + r] = val.y;
        QsT[(c4 + 2) * 64 + r] = val.z;
        QsT[(c4 + 3) * 64 + r] = val.w;
    }
    if (tid < 64) { mrow[tid] = -1e30f; lrow[tid] = 0.f; }
    __syncthreads();

    int qg = tid >> 4, cg = tid & 15;
    float o[4][4] = {};
    float bias0 = ab[h * 2 + 0], bias1 = ab[h * 2 + 1];
    int qvar = qb >> 7;

    for (int kt = 0; kt < 32; kt++) {
        int kb = kt * 64;
        // load K tile transposed
#pragma unroll
        for (int it = 0; it < 4; it++) {
            int idx = tid + it * 256;
            int r = idx >> 4, c4 = (idx & 15) * 4;
            float4 val = *(const float4*)(kp + (size_t)(kb + r) * D_MODEL + c4);
            KsT[(c4 + 0) * 64 + r] = val.x;
            KsT[(c4 + 1) * 64 + r] = val.y;
            KsT[(c4 + 2) * 64 + r] = val.z;
            KsT[(c4 + 3) * 64 + r] = val.w;
        }
        __syncthreads();

        // scores: 4x4 per thread
        float s[4][4] = {};
#pragma unroll 16
        for (int d = 0; d < 64; d++) {
            float4 a = *(const float4*)&QsT[d * 64 + qg * 4];
            float4 kvv = *(const float4*)&KsT[d * 64 + cg * 4];
            s[0][0] += a.x * kvv.x; s[0][1] += a.x * kvv.y; s[0][2] += a.x * kvv.z; s[0][3] += a.x * kvv.w;
            s[1][0] += a.y * kvv.x; s[1][1] += a.y * kvv.y; s[1][2] += a.y * kvv.z; s[1][3] += a.y * kvv.w;
            s[2][0] += a.z * kvv.x; s[2][1] += a.z * kvv.y; s[2][2] += a.z * kvv.z; s[2][3] += a.z * kvv.w;
            s[3][0] += a.w * kvv.x; s[3][1] += a.w * kvv.y; s[3][2] += a.w * kvv.z; s[3][3] += a.w * kvv.w;
        }
        // 64-token tile never crosses a variate (128-token) boundary -> scalar bias
        float bias = ((kb >> 7) == qvar) ? bias0 : bias1;
#pragma unroll
        for (int i = 0; i < 4; i++)
#pragma unroll
            for (int j = 0; j < 4; j++)
                Sc[(qg * 4 + i) * 65 + cg * 4 + j] = s[i][j] + bias;

        // load V tile (row-major) while scores settle
#pragma unroll
        for (int it = 0; it < 4; it++) {
            int idx = tid + it * 256;
            int r = idx >> 4, c4 = (idx & 15) * 4;
            *(float4*)&Vs[r * 64 + c4] = *(const float4*)(vp + (size_t)(kb + r) * D_MODEL + c4);
        }
        __syncthreads();

        // online softmax per query row
        if (tid < 64) {
            float mo = mrow[tid], mx = mo;
            float* sr = &Sc[tid * 65];
#pragma unroll 16
            for (int j = 0; j < 64; j++) mx = fmaxf(mx, sr[j]);
            float scl = expf(mo - mx);
            float sum = 0.f;
#pragma unroll 16
            for (int j = 0; j < 64; j++) {
                float p = expf(sr[j] - mx);
                sr[j] = p;
                sum += p;
            }
            mrow[tid] = mx;
            lrow[tid] = lrow[tid] * scl + sum;
            srow[tid] = scl;
        }
        __syncthreads();

        // rescale accumulators, then O += P @ V
#pragma unroll
        for (int i = 0; i < 4; i++) {
            float scl = srow[qg * 4 + i];
            o[i][0] *= scl; o[i][1] *= scl; o[i][2] *= scl; o[i][3] *= scl;
        }
#pragma unroll 8
        for (int kj = 0; kj < 64; kj++) {
            float4 vv = *(const float4*)&Vs[kj * 64 + cg * 4];
            float p0 = Sc[(qg * 4 + 0) * 65 + kj];
            float p1 = Sc[(qg * 4 + 1) * 65 + kj];
            float p2 = Sc[(qg * 4 + 2) * 65 + kj];
            float p3 = Sc[(qg * 4 + 3) * 65 + kj];
            o[0][0] += p0 * vv.x; o[0][1] += p0 * vv.y; o[0][2] += p0 * vv.z; o[0][3] += p0 * vv.w;
            o[1][0] += p1 * vv.x; o[1][1] += p1 * vv.y; o[1][2] += p1 * vv.z; o[1][3] += p1 * vv.w;
            o[2][0] += p2 * vv.x; o[2][1] += p2 * vv.y; o[2][2] += p2 * vv.z; o[2][3] += p2 * vv.w;
            o[3][0] += p3 * vv.x; o[3][1] += p3 * vv.y; o[3][2] += p3 * vv.z; o[3][3] += p3 * vv.w;
        }
        __syncthreads();
    }

    // normalize and write [B,T,H*hd]
#pragma unroll
    for (int i = 0; i < 4; i++) {
        float inv = 1.f / lrow[qg * 4 + i];
        float4 r = make_float4(o[i][0] * inv, o[i][1] * inv, o[i][2] * inv, o[i][3] * inv);
        *(float4*)(O + (size_t)(b * T_TOK + qb + qg * 4 + i) * D_MODEL + h * HEAD_DIM + cg * 4) = r;
    }
}

// -------------------- launch ----------------------------------------------
extern "C" void kernel_launch(void* const* d_in, const int* in_sizes, int n_in,
                              void* d_out, int out_size) {
    const float* hs  = (const float*)d_in[0];
    const float* wq  = (const float*)d_in[1];
    const float* bq  = (const float*)d_in[2];
    const float* wk  = (const float*)d_in[3];
    const float* bk  = (const float*)d_in[4];
    const float* wv  = (const float*)d_in[5];
    const float* bv  = (const float*)d_in[6];
    const float* wo  = (const float*)d_in[7];
    const float* bo  = (const float*)d_in[8];
    const float* ab  = (const float*)d_in[9];
    const float* g1  = (const float*)d_in[10];
    const float* be1 = (const float*)d_in[11];
    const float* g3  = (const float*)d_in[12];
    const float* be3 = (const float*)d_in[13];
    const float* w1  = (const float*)d_in[14];
    const float* b1  = (const float*)d_in[15];
    const float* w2  = (const float*)d_in[16];
    const float* b2  = (const float*)d_in[17];
    float* out = (float*)d_out;

    float *ni, *q, *k, *v, *attn, *res1, *ffin, *hbuf;
    cudaGetSymbolAddress((void**)&ni,   g_ni);
    cudaGetSymbolAddress((void**)&q,    g_q);
    cudaGetSymbolAddress((void**)&k,    g_k);
    cudaGetSymbolAddress((void**)&v,    g_v);
    cudaGetSymbolAddress((void**)&attn, g_attn);
    cudaGetSymbolAddress((void**)&res1, g_res1);
    cudaGetSymbolAddress((void**)&ffin, g_ffin);
    cudaGetSymbolAddress((void**)&hbuf, g_h);

    static bool attr_set = false;
    if (!attr_set) {
        cudaFuncSetAttribute(attn_kernel, cudaFuncAttributeMaxDynamicSharedMemorySize,
                             ATTN_SMEM_FLOATS * (int)sizeof(float));
        attr_set = true;
    }

    // 1. LN1
    ln_kernel<<<M_ROWS, 256>>>(hs, g1, be1, ni);

    // 2. QKV projections (q pre-scaled by hd^-0.5)
    dim3 gP(D_MODEL / 64, M_ROWS / 64);
    gemm64<false><<<gP, 256>>>(ni, wq, bq, nullptr, q, M_ROWS, D_MODEL, D_MODEL, 0.125f);
    gemm64<false><<<gP, 256>>>(ni, wk, bk, nullptr, k, M_ROWS, D_MODEL, D_MODEL, 1.f);
    gemm64<false><<<gP, 256>>>(ni, wv, bv, nullptr, v, M_ROWS, D_MODEL, D_MODEL, 1.f);

    // 3. RoPE on q,k
    {
        int total = BATCH * T_TOK * N_HEADS * 16;
        rope_kernel<<<(total + 255) / 256, 256>>>(q, k);
    }

    // 4. attention
    {
        dim3 ga(T_TOK / 64, N_HEADS, BATCH);
        attn_kernel<<<ga, 256, ATTN_SMEM_FLOATS * (int)sizeof(float)>>>(q, k, v, ab, attn);
    }

    // 5. out-proj + residual(hs)
    gemm64<false><<<gP, 256>>>(attn, wo, bo, hs, res1, M_ROWS, D_MODEL, D_MODEL, 1.f);

    // 6. LN3
    ln_kernel<<<M_ROWS, 256>>>(res1, g3, be3, ffin);

    // 7. FFN1 + exact GELU
    dim3 gF1(FFN_DIM / 64, M_ROWS / 64);
    gemm64<true><<<gF1, 256>>>(ffin, w1, b1, nullptr, hbuf, M_ROWS, FFN_DIM, D_MODEL, 1.f);

    // 8. FFN2 + residual(res1) -> out
    gemm64<false><<<gP, 256>>>(hbuf, w2, b2, res1, out, M_ROWS, D_MODEL, FFN_DIM, 1.f);
}

// round 2
// speedup vs baseline: 2.5069x; 2.5069x over previous
#include <cuda_runtime.h>
#include <cuda_bf16.h>
#include <math.h>

#define D_MODEL 768
#define N_HEADS 12
#define HEAD_DIM 64
#define FFN_DIM 3072
#define T_TOK 2048
#define BATCH 2
#define M_ROWS (BATCH * T_TOK)   // 4096

// -------------------- scratch ---------------------------------------------
__device__ float g_ni[M_ROWS * D_MODEL];
__device__ float g_q[M_ROWS * D_MODEL];
__device__ float g_k[M_ROWS * D_MODEL];
__device__ float g_v[M_ROWS * D_MODEL];
__device__ float g_attn[M_ROWS * D_MODEL];
__device__ float g_res1[M_ROWS * D_MODEL];
__device__ float g_ffin[M_ROWS * D_MODEL];
__device__ float g_h[M_ROWS * FFN_DIM];

// -------------------- tf32 helpers ----------------------------------------
__device__ __forceinline__ unsigned f2tf32(float f) {
    unsigned u;
    asm("cvt.rna.tf32.f32 %0, %1;" : "=r"(u) : "f"(f));
    return u;
}
__device__ __forceinline__ void sts_tf32x4(unsigned* p, float4 v) {
    uint4 u = make_uint4(f2tf32(v.x), f2tf32(v.y), f2tf32(v.z), f2tf32(v.w));
    *(uint4*)p = u;
}
__device__ __forceinline__ void mma_tf32(float* c, const unsigned* a, const unsigned* b) {
    asm volatile(
        "mma.sync.aligned.m16n8k8.row.col.f32.tf32.tf32.f32 "
        "{%0,%1,%2,%3}, {%4,%5,%6,%7}, {%8,%9}, {%0,%1,%2,%3};"
        : "+f"(c[0]), "+f"(c[1]), "+f"(c[2]), "+f"(c[3])
        : "r"(a[0]), "r"(a[1]), "r"(a[2]), "r"(a[3]), "r"(b[0]), "r"(b[1]));
}

// -------------------- block reduction -------------------------------------
__device__ __forceinline__ float block_sum_256(float val) {
    __shared__ float red[8];
    int lane = threadIdx.x & 31, w = threadIdx.x >> 5;
#pragma unroll
    for (int o = 16; o; o >>= 1) val += __shfl_xor_sync(0xffffffffu, val, o);
    if (lane == 0) red[w] = val;
    __syncthreads();
    if (w == 0) {
        float t = (lane < 8) ? red[lane] : 0.f;
#pragma unroll
        for (int o = 4; o; o >>= 1) t += __shfl_xor_sync(0xffffffffu, t, o);
        if (lane == 0) red[0] = t;
    }
    __syncthreads();
    float r = red[0];
    __syncthreads();
    return r;
}

// -------------------- LayerNorm -------------------------------------------
__global__ void ln_kernel(const float* __restrict__ x, const float* __restrict__ g,
                          const float* __restrict__ bta, float* __restrict__ y) {
    size_t row = blockIdx.x;
    int tid = threadIdx.x;
    const float* xr = x + row * D_MODEL;
    float v0 = xr[tid], v1 = xr[tid + 256], v2 = xr[tid + 512];
    float mu = block_sum_256(v0 + v1 + v2) * (1.f / 768.f);
    float d0 = v0 - mu, d1 = v1 - mu, d2 = v2 - mu;
    float var = block_sum_256(d0 * d0 + d1 * d1 + d2 * d2) * (1.f / 768.f);
    float rs = rsqrtf(var + 1e-5f);
    float* yr = y + row * D_MODEL;
    yr[tid]       = d0 * rs * g[tid]       + bta[tid];
    yr[tid + 256] = d1 * rs * g[tid + 256] + bta[tid + 256];
    yr[tid + 512] = d2 * rs * g[tid + 512] + bta[tid + 512];
}

// -------------------- tf32 GEMM: 128x128x16 tile, 256 threads -------------
// C = epilogue(alpha*(A@B + bias)) (+res). A[M,K], B[K,N] row-major.
#define AS_STRIDE 20
#define BS_STRIDE 136
template <bool GELU>
__global__ __launch_bounds__(256, 2)
void gemm_tf32(const float* __restrict__ A, const float* __restrict__ Bm,
               const float* __restrict__ bias, const float* __restrict__ res,
               float* __restrict__ C, int M, int N, int K, float alpha) {
    __shared__ unsigned As[128 * AS_STRIDE];
    __shared__ unsigned Bs[16 * BS_STRIDE];
    int tid = threadIdx.x;
    int wid = tid >> 5, lane = tid & 31;
    int g = lane >> 2, tig = lane & 3;
    int wm = wid & 3, wn = wid >> 2;           // warp grid 4 x 2
    int brow = blockIdx.y * 128, bcol = blockIdx.x * 128;

    int ar = tid >> 2, ac = (tid & 3) * 4;     // A staging: rows ar, ar+64
    int br = tid >> 5, bc = (tid & 31) * 4;    // B staging: rows br, br+8
    const float* Ap = A + (size_t)(brow + ar) * K + ac;
    const float* Bp = Bm + (size_t)br * N + bcol + bc;

    float4 aR0 = *(const float4*)(Ap);
    float4 aR1 = *(const float4*)(Ap + (size_t)64 * K);
    float4 bR0 = *(const float4*)(Bp);
    float4 bR1 = *(const float4*)(Bp + (size_t)8 * N);

    float acc[2][8][4];
#pragma unroll
    for (int i = 0; i < 2; i++)
#pragma unroll
        for (int j = 0; j < 8; j++)
#pragma unroll
            for (int r = 0; r < 4; r++) acc[i][j][r] = 0.f;

    int nIter = K >> 4;
    for (int kt = 0; kt < nIter; ++kt) {
        __syncthreads();
        sts_tf32x4(&As[ar * AS_STRIDE + ac], aR0);
        sts_tf32x4(&As[(ar + 64) * AS_STRIDE + ac], aR1);
        sts_tf32x4(&Bs[br * BS_STRIDE + bc], bR0);
        sts_tf32x4(&Bs[(br + 8) * BS_STRIDE + bc], bR1);
        __syncthreads();
        if (kt + 1 < nIter) {
            const float* Ap2 = Ap + (kt + 1) * 16;
            aR0 = *(const float4*)(Ap2);
            aR1 = *(const float4*)(Ap2 + (size_t)64 * K);
            const float* Bp2 = Bp + (size_t)(kt + 1) * 16 * N;
            bR0 = *(const float4*)(Bp2);
            bR1 = *(const float4*)(Bp2 + (size_t)8 * N);
        }
#pragma unroll
        for (int ks = 0; ks < 16; ks += 8) {
            unsigned af[2][4];
#pragma unroll
            for (int mt = 0; mt < 2; mt++) {
                int r0 = wm * 32 + mt * 16 + g;
                af[mt][0] = As[r0 * AS_STRIDE + ks + tig];
                af[mt][1] = As[(r0 + 8) * AS_STRIDE + ks + tig];
                af[mt][2] = As[r0 * AS_STRIDE + ks + tig + 4];
                af[mt][3] = As[(r0 + 8) * AS_STRIDE + ks + tig + 4];
            }
#pragma unroll
            for (int nt = 0; nt < 8; nt++) {
                unsigned bf[2];
                int c0 = wn * 64 + nt * 8 + g;
                bf[0] = Bs[(ks + tig) * BS_STRIDE + c0];
                bf[1] = Bs[(ks + tig + 4) * BS_STRIDE + c0];
                mma_tf32(acc[0][nt], af[0], bf);
                mma_tf32(acc[1][nt], af[1], bf);
            }
        }
    }

    // epilogue
#pragma unroll
    for (int mt = 0; mt < 2; mt++) {
        int row0 = brow + wm * 32 + mt * 16 + g;
#pragma unroll
        for (int nt = 0; nt < 8; nt++) {
            int col = bcol + wn * 64 + nt * 8 + tig * 2;
            float b0 = bias[col], b1 = bias[col + 1];
            float v00 = alpha * (acc[mt][nt][0] + b0);
            float v01 = alpha * (acc[mt][nt][1] + b1);
            float v10 = alpha * (acc[mt][nt][2] + b0);
            float v11 = alpha * (acc[mt][nt][3] + b1);
            if (GELU) {
                v00 *= normcdff(v00); v01 *= normcdff(v01);
                v10 *= normcdff(v10); v11 *= normcdff(v11);
            }
            if (res) {
                const float* r0p = res + (size_t)row0 * N + col;
                const float* r1p = res + (size_t)(row0 + 8) * N + col;
                v00 += r0p[0]; v01 += r0p[1];
                v10 += r1p[0]; v11 += r1p[1];
            }
            *(float2*)(C + (size_t)row0 * N + col) = make_float2(v00, v01);
            *(float2*)(C + (size_t)(row0 + 8) * N + col) = make_float2(v10, v11);
        }
    }
}

// -------------------- p-RoPE ----------------------------------------------
__global__ void rope_kernel(float* __restrict__ q, float* __restrict__ k) {
    int idx = blockIdx.x * blockDim.x + threadIdx.x;
    const int total = BATCH * T_TOK * N_HEADS * 16;
    if (idx >= total) return;
    int i = idx & 15;
    int h = (idx >> 4) % N_HEADS;
    int t = (idx / (16 * N_HEADS)) % T_TOK;
    int b = idx / (16 * N_HEADS * T_TOK);
    size_t base = ((size_t)(b * T_TOK + t)) * D_MODEL + h * HEAD_DIM + i;
    double ts = pow(10000.0, (double)i / 32.0);
    double ang = (double)t / ts;
    double sd, cd;
    sincos(ang, &sd, &cd);
    float sf = (float)sd, cf = (float)cd;
    float x1 = q[base], x2 = q[base + 32];
    q[base]      = x1 * cf - x2 * sf;
    q[base + 32] = x2 * cf + x1 * sf;
    x1 = k[base]; x2 = k[base + 32];
    k[base]      = x1 * cf - x2 * sf;
    k[base + 32] = x2 * cf + x1 * sf;
}

// -------------------- flash attention with tf32 MMA ------------------------
// grid (T/64, H, B), 256 threads = 8 warps. Warp tile: 16 q-rows x 32 cols.
#define QS_STRIDE 68
#define KS_STRIDE 76
#define VS_STRIDE 72
#define SC_STRIDE 68
#define AT_SMEM_FLOATS (64*QS_STRIDE + 64*KS_STRIDE + 64*VS_STRIDE + 64*SC_STRIDE + 192)

__global__ __launch_bounds__(256)
void attn_tf32(const float* __restrict__ Q, const float* __restrict__ Kk,
               const float* __restrict__ V, const float* __restrict__ ab,
               float* __restrict__ O) {
    extern __shared__ float sm[];
    unsigned* Qs = (unsigned*)sm;                   // [64][68] token x dim
    unsigned* Ks = Qs + 64 * QS_STRIDE;             // [64][76] token x dim
    unsigned* Vs = Ks + 64 * KS_STRIDE;             // [64][72] token x dim
    float* Sc = (float*)(Vs + 64 * VS_STRIDE);      // [64][68]
    float* mrow = Sc + 64 * SC_STRIDE;
    float* lrow = mrow + 64;
    float* srow = lrow + 64;

    int tid = threadIdx.x;
    int wid = tid >> 5, lane = tid & 31;
    int g = lane >> 2, tig = lane & 3;
    int m0 = (wid >> 1) * 16;
    int n0b = (wid & 1) * 32;

    int qb = blockIdx.x * 64;
    int h = blockIdx.y, b = blockIdx.z;
    size_t bh = (size_t)b * T_TOK * D_MODEL + h * HEAD_DIM;
    const float* qp = Q + bh;
    const float* kp = Kk + bh;
    const float* vp = V + bh;

#pragma unroll
    for (int it = 0; it < 4; it++) {
        int idx = tid + it * 256;
        int r = idx >> 4, c4 = (idx & 15) * 4;
        float4 v = *(const float4*)(qp + (size_t)(qb + r) * D_MODEL + c4);
        sts_tf32x4(&Qs[r * QS_STRIDE + c4], v);
    }
    if (tid < 64) { mrow[tid] = -1e30f; lrow[tid] = 0.f; }
    __syncthreads();

    float o[4][4];
#pragma unroll
    for (int i = 0; i < 4; i++)
#pragma unroll
        for (int j = 0; j < 4; j++) o[i][j] = 0.f;

    float bias0 = ab[h * 2 + 0], bias1 = ab[h * 2 + 1];
    int qvar = qb >> 7;

    for (int kt = 0; kt < 32; kt++) {
        int kb = kt * 64;
        // stage K, V (prev iteration's consumers finished at loop-end sync)
#pragma unroll
        for (int it = 0; it < 4; it++) {
            int idx = tid + it * 256;
            int r = idx >> 4, c4 = (idx & 15) * 4;
            float4 kv = *(const float4*)(kp + (size_t)(kb + r) * D_MODEL + c4);
            sts_tf32x4(&Ks[r * KS_STRIDE + c4], kv);
            float4 vv = *(const float4*)(vp + (size_t)(kb + r) * D_MODEL + c4);
            sts_tf32x4(&Vs[r * VS_STRIDE + c4], vv);
        }
        __syncthreads();

        // ---- S = Q @ K^T via mma ----
        float s[4][4];
#pragma unroll
        for (int i = 0; i < 4; i++)
#pragma unroll
            for (int j = 0; j < 4; j++) s[i][j] = 0.f;
#pragma unroll
        for (int ks = 0; ks < 64; ks += 8) {
            unsigned af[4];
            af[0] = Qs[(m0 + g) * QS_STRIDE + ks + tig];
            af[1] = Qs[(m0 + g + 8) * QS_STRIDE + ks + tig];
            af[2] = Qs[(m0 + g) * QS_STRIDE + ks + tig + 4];
            af[3] = Qs[(m0 + g + 8) * QS_STRIDE + ks + tig + 4];
#pragma unroll
            for (int nt = 0; nt < 4; nt++) {
                unsigned bf[2];
                int c0 = n0b + nt * 8 + g;
                bf[0] = Ks[c0 * KS_STRIDE + ks + tig];
                bf[1] = Ks[c0 * KS_STRIDE + ks + tig + 4];
                mma_tf32(s[nt], af, bf);
            }
        }
        float bias = ((kb >> 7) == qvar) ? bias0 : bias1;
#pragma unroll
        for (int nt = 0; nt < 4; nt++) {
            int col = n0b + nt * 8 + tig * 2;
            Sc[(m0 + g) * SC_STRIDE + col]     = s[nt][0] + bias;
            Sc[(m0 + g) * SC_STRIDE + col + 1] = s[nt][1] + bias;
            Sc[(m0 + g + 8) * SC_STRIDE + col]     = s[nt][2] + bias;
            Sc[(m0 + g + 8) * SC_STRIDE + col + 1] = s[nt][3] + bias;
        }
        __syncthreads();

        // ---- online softmax ----
        if (tid < 64) {
            float mo = mrow[tid], mx = mo;
            float* sr = &Sc[tid * SC_STRIDE];
#pragma unroll 16
            for (int j = 0; j < 64; j++) mx = fmaxf(mx, sr[j]);
            float scl = expf(mo - mx);
            float sum = 0.f;
#pragma unroll 16
            for (int j = 0; j < 64; j++) {
                float p = expf(sr[j] - mx);
                sr[j] = p;
                sum += p;
            }
            mrow[tid] = mx;
            lrow[tid] = lrow[tid] * scl + sum;
            srow[tid] = scl;
        }
        __syncthreads();

        // ---- rescale + O += P @ V via mma ----
        float scl0 = srow[m0 + g], scl1 = srow[m0 + g + 8];
#pragma unroll
        for (int nt = 0; nt < 4; nt++) {
            o[nt][0] *= scl0; o[nt][1] *= scl0;
            o[nt][2] *= scl1; o[nt][3] *= scl1;
        }
#pragma unroll
        for (int ks = 0; ks < 64; ks += 8) {
            unsigned af[4];
            af[0] = f2tf32(Sc[(m0 + g) * SC_STRIDE + ks + tig]);
            af[1] = f2tf32(Sc[(m0 + g + 8) * SC_STRIDE + ks + tig]);
            af[2] = f2tf32(Sc[(m0 + g) * SC_STRIDE + ks + tig + 4]);
            af[3] = f2tf32(Sc[(m0 + g + 8) * SC_STRIDE + ks + tig + 4]);
#pragma unroll
            for (int nt = 0; nt < 4; nt++) {
                unsigned bf[2];
                int c0 = n0b + nt * 8 + g;
                bf[0] = Vs[(ks + tig) * VS_STRIDE + c0];
                bf[1] = Vs[(ks + tig + 4) * VS_STRIDE + c0];
                mma_tf32(o[nt], af, bf);
            }
        }
        __syncthreads();
    }

    // ---- normalize + write ----
    float inv0 = 1.f / lrow[m0 + g], inv1 = 1.f / lrow[m0 + g + 8];
    int row0 = qb + m0 + g;
#pragma unroll
    for (int nt = 0; nt < 4; nt++) {
        int col = n0b + nt * 8 + tig * 2;
        float* o0 = O + (size_t)(b * T_TOK + row0) * D_MODEL + h * HEAD_DIM + col;
        float* o1 = O + (size_t)(b * T_TOK + row0 + 8) * D_MODEL + h * HEAD_DIM + col;
        *(float2*)o0 = make_float2(o[nt][0] * inv0, o[nt][1] * inv0);
        *(float2*)o1 = make_float2(o[nt][2] * inv1, o[nt][3] * inv1);
    }
}

// -------------------- launch ----------------------------------------------
extern "C" void kernel_launch(void* const* d_in, const int* in_sizes, int n_in,
                              void* d_out, int out_size) {
    const float* hs  = (const float*)d_in[0];
    const float* wq  = (const float*)d_in[1];
    const float* bq  = (const float*)d_in[2];
    const float* wk  = (const float*)d_in[3];
    const float* bk  = (const float*)d_in[4];
    const float* wv  = (const float*)d_in[5];
    const float* bv  = (const float*)d_in[6];
    const float* wo  = (const float*)d_in[7];
    const float* bo  = (const float*)d_in[8];
    const float* ab  = (const float*)d_in[9];
    const float* g1  = (const float*)d_in[10];
    const float* be1 = (const float*)d_in[11];
    const float* g3  = (const float*)d_in[12];
    const float* be3 = (const float*)d_in[13];
    const float* w1  = (const float*)d_in[14];
    const float* b1  = (const float*)d_in[15];
    const float* w2  = (const float*)d_in[16];
    const float* b2  = (const float*)d_in[17];
    float* out = (float*)d_out;

    float *ni, *q, *k, *v, *attn, *res1, *ffin, *hbuf;
    cudaGetSymbolAddress((void**)&ni,   g_ni);
    cudaGetSymbolAddress((void**)&q,    g_q);
    cudaGetSymbolAddress((void**)&k,    g_k);
    cudaGetSymbolAddress((void**)&v,    g_v);
    cudaGetSymbolAddress((void**)&attn, g_attn);
    cudaGetSymbolAddress((void**)&res1, g_res1);
    cudaGetSymbolAddress((void**)&ffin, g_ffin);
    cudaGetSymbolAddress((void**)&hbuf, g_h);

    static bool attr_set = false;
    if (!attr_set) {
        cudaFuncSetAttribute(attn_tf32, cudaFuncAttributeMaxDynamicSharedMemorySize,
                             AT_SMEM_FLOATS * (int)sizeof(float));
        attr_set = true;
    }

    // 1. LN1
    ln_kernel<<<M_ROWS, 256>>>(hs, g1, be1, ni);

    // 2. QKV projections (q pre-scaled by hd^-0.5 via alpha)
    dim3 gP(D_MODEL / 128, M_ROWS / 128);
    gemm_tf32<false><<<gP, 256>>>(ni, wq, bq, nullptr, q, M_ROWS, D_MODEL, D_MODEL, 0.125f);
    gemm_tf32<false><<<gP, 256>>>(ni, wk, bk, nullptr, k, M_ROWS, D_MODEL, D_MODEL, 1.f);
    gemm_tf32<false><<<gP, 256>>>(ni, wv, bv, nullptr, v, M_ROWS, D_MODEL, D_MODEL, 1.f);

    // 3. RoPE
    {
        int total = BATCH * T_TOK * N_HEADS * 16;
        rope_kernel<<<(total + 255) / 256, 256>>>(q, k);
    }

    // 4. attention
    {
        dim3 ga(T_TOK / 64, N_HEADS, BATCH);
        attn_tf32<<<ga, 256, AT_SMEM_FLOATS * (int)sizeof(float)>>>(q, k, v, ab, attn);
    }

    // 5. out-proj + residual(hs)
    gemm_tf32<false><<<gP, 256>>>(attn, wo, bo, hs, res1, M_ROWS, D_MODEL, D_MODEL, 1.f);

    // 6. LN3
    ln_kernel<<<M_ROWS, 256>>>(res1, g3, be3, ffin);

    // 7. FFN1 + exact GELU
    dim3 gF1(FFN_DIM / 128, M_ROWS / 128);
    gemm_tf32<true><<<gF1, 256>>>(ffin, w1, b1, nullptr, hbuf, M_ROWS, FFN_DIM, D_MODEL, 1.f);

    // 8. FFN2 + residual(res1) -> out
    gemm_tf32<false><<<gP, 256>>>(hbuf, w2, b2, res1, out, M_ROWS, D_MODEL, FFN_DIM, 1.f);
}

// round 3
// speedup vs baseline: 2.7663x; 1.1035x over previous
#include <cuda_runtime.h>
#include <cuda_bf16.h>
#include <math.h>

#define D_MODEL 768
#define N_HEADS 12
#define HEAD_DIM 64
#define FFN_DIM 3072
#define T_TOK 2048
#define BATCH 2
#define M_ROWS (BATCH * T_TOK)   // 4096
#define QKV_N 2304               // 3 * D_MODEL

// -------------------- scratch ---------------------------------------------
__device__ float g_ni[M_ROWS * D_MODEL];
__device__ float g_qkv[M_ROWS * QKV_N];
__device__ float g_wqkv[D_MODEL * QKV_N];
__device__ float g_bqkv[QKV_N];
__device__ float g_attn[M_ROWS * D_MODEL];
__device__ float g_res1[M_ROWS * D_MODEL];
__device__ float g_ffin[M_ROWS * D_MODEL];
__device__ float g_h[M_ROWS * FFN_DIM];

// -------------------- async copy helpers ----------------------------------
__device__ __forceinline__ void cp16(void* smem_dst, const void* gptr) {
    unsigned a = (unsigned)__cvta_generic_to_shared(smem_dst);
    asm volatile("cp.async.ca.shared.global [%0], [%1], 16;" :: "r"(a), "l"(gptr));
}
__device__ __forceinline__ void cp_commit() { asm volatile("cp.async.commit_group;"); }
template <int NN>
__device__ __forceinline__ void cp_wait() { asm volatile("cp.async.wait_group %0;" :: "n"(NN)); }

__device__ __forceinline__ void mma_tf32(float* c, const unsigned* a, const unsigned* b) {
    asm volatile(
        "mma.sync.aligned.m16n8k8.row.col.f32.tf32.tf32.f32 "
        "{%0,%1,%2,%3}, {%4,%5,%6,%7}, {%8,%9}, {%0,%1,%2,%3};"
        : "+f"(c[0]), "+f"(c[1]), "+f"(c[2]), "+f"(c[3])
        : "r"(a[0]), "r"(a[1]), "r"(a[2]), "r"(a[3]), "r"(b[0]), "r"(b[1]));
}

// -------------------- block reduction -------------------------------------
__device__ __forceinline__ float block_sum_256(float val) {
    __shared__ float red[8];
    int lane = threadIdx.x & 31, w = threadIdx.x >> 5;
#pragma unroll
    for (int o = 16; o; o >>= 1) val += __shfl_xor_sync(0xffffffffu, val, o);
    if (lane == 0) red[w] = val;
    __syncthreads();
    if (w == 0) {
        float t = (lane < 8) ? red[lane] : 0.f;
#pragma unroll
        for (int o = 4; o; o >>= 1) t += __shfl_xor_sync(0xffffffffu, t, o);
        if (lane == 0) red[0] = t;
    }
    __syncthreads();
    float r = red[0];
    __syncthreads();
    return r;
}

// -------------------- LayerNorm -------------------------------------------
__global__ void ln_kernel(const float* __restrict__ x, const float* __restrict__ g,
                          const float* __restrict__ bta, float* __restrict__ y) {
    size_t row = blockIdx.x;
    int tid = threadIdx.x;
    const float* xr = x + row * D_MODEL;
    float v0 = xr[tid], v1 = xr[tid + 256], v2 = xr[tid + 512];
    float mu = block_sum_256(v0 + v1 + v2) * (1.f / 768.f);
    float d0 = v0 - mu, d1 = v1 - mu, d2 = v2 - mu;
    float var = block_sum_256(d0 * d0 + d1 * d1 + d2 * d2) * (1.f / 768.f);
    float rs = rsqrtf(var + 1e-5f);
    float* yr = y + row * D_MODEL;
    yr[tid]       = d0 * rs * g[tid]       + bta[tid];
    yr[tid + 256] = d1 * rs * g[tid + 256] + bta[tid + 256];
    yr[tid + 512] = d2 * rs * g[tid + 512] + bta[tid + 512];
}

// -------------------- QKV weight/bias concat (q scaled by 0.125) ----------
__global__ void concat_qkv(const float* __restrict__ wq, const float* __restrict__ wk,
                           const float* __restrict__ wv, const float* __restrict__ bq,
                           const float* __restrict__ bk, const float* __restrict__ bv,
                           float* __restrict__ W, float* __restrict__ Bo) {
    int idx = blockIdx.x * 256 + threadIdx.x;           // float4 index
    const int total = D_MODEL * QKV_N / 4;
    if (idx < total) {
        int e = idx * 4;
        int k = e / QKV_N, j = e % QKV_N;
        float4 v;
        if (j < 768) {
            v = *(const float4*)(wq + (size_t)k * 768 + j);
            v.x *= 0.125f; v.y *= 0.125f; v.z *= 0.125f; v.w *= 0.125f;
        } else if (j < 1536) {
            v = *(const float4*)(wk + (size_t)k * 768 + (j - 768));
        } else {
            v = *(const float4*)(wv + (size_t)k * 768 + (j - 1536));
        }
        *(float4*)(W + e) = v;
    }
    if (idx < QKV_N / 4) {
        int j = idx * 4;
        float4 v;
        if (j < 768) {
            v = *(const float4*)(bq + j);
            v.x *= 0.125f; v.y *= 0.125f; v.z *= 0.125f; v.w *= 0.125f;
        } else if (j < 1536) {
            v = *(const float4*)(bk + (j - 768));
        } else {
            v = *(const float4*)(bv + (j - 1536));
        }
        *(float4*)(Bo + j) = v;
    }
}

// -------------------- tf32 GEMM: cp.async double-buffered ------------------
// C = epilogue(A@B + bias) (+res). A[M,K], B[K,N] row-major, raw fp32 bits
// fed to tf32 mma (HW truncates mantissa).
#define AS_STRIDE 20
#define BS_STRIDE 136
template <bool GELU>
__global__ __launch_bounds__(256, 2)
void gemm_tf32(const float* __restrict__ A, const float* __restrict__ Bm,
               const float* __restrict__ bias, const float* __restrict__ res,
               float* __restrict__ C, int M, int N, int K) {
    __shared__ unsigned As[2][128 * AS_STRIDE];
    __shared__ unsigned Bs[2][16 * BS_STRIDE];
    int tid = threadIdx.x;
    int wid = tid >> 5, lane = tid & 31;
    int g = lane >> 2, tig = lane & 3;
    int wm = wid & 3, wn = wid >> 2;           // warp grid 4 x 2
    int brow = blockIdx.y * 128, bcol = blockIdx.x * 128;

    int ar = tid >> 2, ac = (tid & 3) * 4;
    int br = tid >> 5, bc = (tid & 31) * 4;
    const float* Ap = A + (size_t)(brow + ar) * K + ac;
    const float* Bp = Bm + (size_t)br * N + bcol + bc;

    int nIter = K >> 4;
    // prologue: stage 0
    {
        cp16(&As[0][ar * AS_STRIDE + ac], Ap);
        cp16(&As[0][(ar + 64) * AS_STRIDE + ac], Ap + (size_t)64 * K);
        cp16(&Bs[0][br * BS_STRIDE + bc], Bp);
        cp16(&Bs[0][(br + 8) * BS_STRIDE + bc], Bp + (size_t)8 * N);
        cp_commit();
    }

    float acc[2][8][4];
#pragma unroll
    for (int i = 0; i < 2; i++)
#pragma unroll
        for (int j = 0; j < 8; j++)
#pragma unroll
            for (int r = 0; r < 4; r++) acc[i][j][r] = 0.f;

    for (int kt = 0; kt < nIter; ++kt) {
        int cur = kt & 1;
        if (kt + 1 < nIter) {
            int nxt = cur ^ 1;
            const float* a0 = Ap + (kt + 1) * 16;
            const float* b0 = Bp + (size_t)(kt + 1) * 16 * N;
            cp16(&As[nxt][ar * AS_STRIDE + ac], a0);
            cp16(&As[nxt][(ar + 64) * AS_STRIDE + ac], a0 + (size_t)64 * K);
            cp16(&Bs[nxt][br * BS_STRIDE + bc], b0);
            cp16(&Bs[nxt][(br + 8) * BS_STRIDE + bc], b0 + (size_t)8 * N);
            cp_commit();
            cp_wait<1>();
        } else {
            cp_wait<0>();
        }
        __syncthreads();
#pragma unroll
        for (int ks = 0; ks < 16; ks += 8) {
            unsigned af[2][4];
#pragma unroll
            for (int mt = 0; mt < 2; mt++) {
                int r0 = wm * 32 + mt * 16 + g;
                af[mt][0] = As[cur][r0 * AS_STRIDE + ks + tig];
                af[mt][1] = As[cur][(r0 + 8) * AS_STRIDE + ks + tig];
                af[mt][2] = As[cur][r0 * AS_STRIDE + ks + tig + 4];
                af[mt][3] = As[cur][(r0 + 8) * AS_STRIDE + ks + tig + 4];
            }
#pragma unroll
            for (int nt = 0; nt < 8; nt++) {
                unsigned bf[2];
                int c0 = wn * 64 + nt * 8 + g;
                bf[0] = Bs[cur][(ks + tig) * BS_STRIDE + c0];
                bf[1] = Bs[cur][(ks + tig + 4) * BS_STRIDE + c0];
                mma_tf32(acc[0][nt], af[0], bf);
                mma_tf32(acc[1][nt], af[1], bf);
            }
        }
        __syncthreads();
    }

    // epilogue
#pragma unroll
    for (int mt = 0; mt < 2; mt++) {
        int row0 = brow + wm * 32 + mt * 16 + g;
#pragma unroll
        for (int nt = 0; nt < 8; nt++) {
            int col = bcol + wn * 64 + nt * 8 + tig * 2;
            float b0 = bias[col], b1 = bias[col + 1];
            float v00 = acc[mt][nt][0] + b0;
            float v01 = acc[mt][nt][1] + b1;
            float v10 = acc[mt][nt][2] + b0;
            float v11 = acc[mt][nt][3] + b1;
            if (GELU) {
                v00 *= normcdff(v00); v01 *= normcdff(v01);
                v10 *= normcdff(v10); v11 *= normcdff(v11);
            }
            if (res) {
                const float* r0p = res + (size_t)row0 * N + col;
                const float* r1p = res + (size_t)(row0 + 8) * N + col;
                v00 += r0p[0]; v01 += r0p[1];
                v10 += r1p[0]; v11 += r1p[1];
            }
            *(float2*)(C + (size_t)row0 * N + col) = make_float2(v00, v01);
            *(float2*)(C + (size_t)(row0 + 8) * N + col) = make_float2(v10, v11);
        }
    }
}

// -------------------- p-RoPE on fused qkv buffer ---------------------------
__global__ void rope_kernel(float* __restrict__ qkv) {
    int idx = blockIdx.x * blockDim.x + threadIdx.x;
    const int total = BATCH * T_TOK * N_HEADS * 16;
    if (idx >= total) return;
    int i = idx & 15;
    int h = (idx >> 4) % N_HEADS;
    int t = (idx / (16 * N_HEADS)) % T_TOK;
    int b = idx / (16 * N_HEADS * T_TOK);
    size_t base = ((size_t)(b * T_TOK + t)) * QKV_N + h * HEAD_DIM + i;
    double ts = pow(10000.0, (double)i / 32.0);
    double ang = (double)t / ts;
    double sd, cd;
    sincos(ang, &sd, &cd);
    float sf = (float)sd, cf = (float)cd;
    float x1 = qkv[base], x2 = qkv[base + 32];          // q
    qkv[base]      = x1 * cf - x2 * sf;
    qkv[base + 32] = x2 * cf + x1 * sf;
    x1 = qkv[base + 768]; x2 = qkv[base + 800];          // k
    qkv[base + 768] = x1 * cf - x2 * sf;
    qkv[base + 800] = x2 * cf + x1 * sf;
}

// -------------------- flash attention (tf32 mma, raw fp32 bits) -----------
#define QS_STRIDE 68
#define KS_STRIDE 76
#define VS_STRIDE 72
#define SC_STRIDE 68
#define AT_SMEM_FLOATS (64*QS_STRIDE + 64*KS_STRIDE + 64*VS_STRIDE + 64*SC_STRIDE + 192)

__global__ __launch_bounds__(256)
void attn_tf32(const float* __restrict__ QKV, const float* __restrict__ ab,
               float* __restrict__ O) {
    extern __shared__ float sm[];
    unsigned* Qs = (unsigned*)sm;
    unsigned* Ks = Qs + 64 * QS_STRIDE;
    unsigned* Vs = Ks + 64 * KS_STRIDE;
    float* Sc = (float*)(Vs + 64 * VS_STRIDE);
    float* mrow = Sc + 64 * SC_STRIDE;
    float* lrow = mrow + 64;
    float* srow = lrow + 64;
    unsigned* Scu = (unsigned*)Sc;

    int tid = threadIdx.x;
    int wid = tid >> 5, lane = tid & 31;
    int g = lane >> 2, tig = lane & 3;
    int m0 = (wid >> 1) * 16;
    int n0b = (wid & 1) * 32;

    int qb = blockIdx.x * 64;
    int h = blockIdx.y, b = blockIdx.z;
    size_t bh = (size_t)b * T_TOK * QKV_N + h * HEAD_DIM;
    const float* qp = QKV + bh;
    const float* kp = QKV + bh + 768;
    const float* vp = QKV + bh + 1536;

#pragma unroll
    for (int it = 0; it < 4; it++) {
        int idx = tid + it * 256;
        int r = idx >> 4, c4 = (idx & 15) * 4;
        cp16(&Qs[r * QS_STRIDE + c4], qp + (size_t)(qb + r) * QKV_N + c4);
    }
    cp_commit();
    if (tid < 64) { mrow[tid] = -1e30f; lrow[tid] = 0.f; }

    float o[4][4];
#pragma unroll
    for (int i = 0; i < 4; i++)
#pragma unroll
        for (int j = 0; j < 4; j++) o[i][j] = 0.f;

    float bias0 = ab[h * 2 + 0], bias1 = ab[h * 2 + 1];
    int qvar = qb >> 7;

    for (int kt = 0; kt < 32; kt++) {
        int kb = kt * 64;
#pragma unroll
        for (int it = 0; it < 4; it++) {
            int idx = tid + it * 256;
            int r = idx >> 4, c4 = (idx & 15) * 4;
            cp16(&Ks[r * KS_STRIDE + c4], kp + (size_t)(kb + r) * QKV_N + c4);
            cp16(&Vs[r * VS_STRIDE + c4], vp + (size_t)(kb + r) * QKV_N + c4);
        }
        cp_commit();
        cp_wait<0>();
        __syncthreads();

        // ---- S = Q @ K^T ----
        float s[4][4];
#pragma unroll
        for (int i = 0; i < 4; i++)
#pragma unroll
            for (int j = 0; j < 4; j++) s[i][j] = 0.f;
#pragma unroll
        for (int ks = 0; ks < 64; ks += 8) {
            unsigned af[4];
            af[0] = Qs[(m0 + g) * QS_STRIDE + ks + tig];
            af[1] = Qs[(m0 + g + 8) * QS_STRIDE + ks + tig];
            af[2] = Qs[(m0 + g) * QS_STRIDE + ks + tig + 4];
            af[3] = Qs[(m0 + g + 8) * QS_STRIDE + ks + tig + 4];
#pragma unroll
            for (int nt = 0; nt < 4; nt++) {
                unsigned bf[2];
                int c0 = n0b + nt * 8 + g;
                bf[0] = Ks[c0 * KS_STRIDE + ks + tig];
                bf[1] = Ks[c0 * KS_STRIDE + ks + tig + 4];
                mma_tf32(s[nt], af, bf);
            }
        }
        float bias = ((kb >> 7) == qvar) ? bias0 : bias1;
#pragma unroll
        for (int nt = 0; nt < 4; nt++) {
            int col = n0b + nt * 8 + tig * 2;
            Sc[(m0 + g) * SC_STRIDE + col]     = s[nt][0] + bias;
            Sc[(m0 + g) * SC_STRIDE + col + 1] = s[nt][1] + bias;
            Sc[(m0 + g + 8) * SC_STRIDE + col]     = s[nt][2] + bias;
            Sc[(m0 + g + 8) * SC_STRIDE + col + 1] = s[nt][3] + bias;
        }
        __syncthreads();

        // ---- online softmax: 4 threads per row, 16 cols each ----
        {
            int r = tid >> 2, seg = tid & 3;
            float* sr = &Sc[r * SC_STRIDE + seg * 16];
            float mo = mrow[r];
            float mx = -1e30f;
#pragma unroll
            for (int j = 0; j < 16; j++) mx = fmaxf(mx, sr[j]);
            mx = fmaxf(mx, __shfl_xor_sync(0xffffffffu, mx, 1));
            mx = fmaxf(mx, __shfl_xor_sync(0xffffffffu, mx, 2));
            mx = fmaxf(mx, mo);
            float sum = 0.f;
#pragma unroll
            for (int j = 0; j < 16; j++) {
                float p = expf(sr[j] - mx);
                sr[j] = p;
                sum += p;
            }
            sum += __shfl_xor_sync(0xffffffffu, sum, 1);
            sum += __shfl_xor_sync(0xffffffffu, sum, 2);
            if (seg == 0) {
                float scl = expf(mo - mx);
                mrow[r] = mx;
                lrow[r] = lrow[r] * scl + sum;
                srow[r] = scl;
            }
        }
        __syncthreads();

        // ---- rescale + O += P @ V ----
        float scl0 = srow[m0 + g], scl1 = srow[m0 + g + 8];
#pragma unroll
        for (int nt = 0; nt < 4; nt++) {
            o[nt][0] *= scl0; o[nt][1] *= scl0;
            o[nt][2] *= scl1; o[nt][3] *= scl1;
        }
#pragma unroll
        for (int ks = 0; ks < 64; ks += 8) {
            unsigned af[4];
            af[0] = Scu[(m0 + g) * SC_STRIDE + ks + tig];
            af[1] = Scu[(m0 + g + 8) * SC_STRIDE + ks + tig];
            af[2] = Scu[(m0 + g) * SC_STRIDE + ks + tig + 4];
            af[3] = Scu[(m0 + g + 8) * SC_STRIDE + ks + tig + 4];
#pragma unroll
            for (int nt = 0; nt < 4; nt++) {
                unsigned bf[2];
                int c0 = n0b + nt * 8 + g;
                bf[0] = Vs[(ks + tig) * VS_STRIDE + c0];
                bf[1] = Vs[(ks + tig + 4) * VS_STRIDE + c0];
                mma_tf32(o[nt], af, bf);
            }
        }
        __syncthreads();
    }

    float inv0 = 1.f / lrow[m0 + g], inv1 = 1.f / lrow[m0 + g + 8];
    int row0 = qb + m0 + g;
#pragma unroll
    for (int nt = 0; nt < 4; nt++) {
        int col = n0b + nt * 8 + tig * 2;
        float* o0 = O + (size_t)(b * T_TOK + row0) * D_MODEL + h * HEAD_DIM + col;
        float* o1 = O + (size_t)(b * T_TOK + row0 + 8) * D_MODEL + h * HEAD_DIM + col;
        *(float2*)o0 = make_float2(o[nt][0] * inv0, o[nt][1] * inv0);
        *(float2*)o1 = make_float2(o[nt][2] * inv1, o[nt][3] * inv1);
    }
}

// -------------------- launch ----------------------------------------------
extern "C" void kernel_launch(void* const* d_in, const int* in_sizes, int n_in,
                              void* d_out, int out_size) {
    const float* hs  = (const float*)d_in[0];
    const float* wq  = (const float*)d_in[1];
    const float* bq  = (const float*)d_in[2];
    const float* wk  = (const float*)d_in[3];
    const float* bk  = (const float*)d_in[4];
    const float* wv  = (const float*)d_in[5];
    const float* bv  = (const float*)d_in[6];
    const float* wo  = (const float*)d_in[7];
    const float* bo  = (const float*)d_in[8];
    const float* ab  = (const float*)d_in[9];
    const float* g1  = (const float*)d_in[10];
    const float* be1 = (const float*)d_in[11];
    const float* g3  = (const float*)d_in[12];
    const float* be3 = (const float*)d_in[13];
    const float* w1  = (const float*)d_in[14];
    const float* b1  = (const float*)d_in[15];
    const float* w2  = (const float*)d_in[16];
    const float* b2  = (const float*)d_in[17];
    float* out = (float*)d_out;

    float *ni, *qkv, *wqkv, *bqkv, *attn, *res1, *ffin, *hbuf;
    cudaGetSymbolAddress((void**)&ni,   g_ni);
    cudaGetSymbolAddress((void**)&qkv,  g_qkv);
    cudaGetSymbolAddress((void**)&wqkv, g_wqkv);
    cudaGetSymbolAddress((void**)&bqkv, g_bqkv);
    cudaGetSymbolAddress((void**)&attn, g_attn);
    cudaGetSymbolAddress((void**)&res1, g_res1);
    cudaGetSymbolAddress((void**)&ffin, g_ffin);
    cudaGetSymbolAddress((void**)&hbuf, g_h);

    static bool attr_set = false;
    if (!attr_set) {
        cudaFuncSetAttribute(attn_tf32, cudaFuncAttributeMaxDynamicSharedMemorySize,
                             AT_SMEM_FLOATS * (int)sizeof(float));
        attr_set = true;
    }

    // 0. concat QKV weights (scales q by 0.125)
    concat_qkv<<<(D_MODEL * QKV_N / 4 + 255) / 256, 256>>>(wq, wk, wv, bq, bk, bv, wqkv, bqkv);

    // 1. LN1
    ln_kernel<<<M_ROWS, 256>>>(hs, g1, be1, ni);

    // 2. fused QKV projection
    dim3 gQKV(QKV_N / 128, M_ROWS / 128);
    gemm_tf32<false><<<gQKV, 256>>>(ni, wqkv, bqkv, nullptr, qkv, M_ROWS, QKV_N, D_MODEL);

    // 3. RoPE
    {
        int total = BATCH * T_TOK * N_HEADS * 16;
        rope_kernel<<<(total + 255) / 256, 256>>>(qkv);
    }

    // 4. attention
    {
        dim3 ga(T_TOK / 64, N_HEADS, BATCH);
        attn_tf32<<<ga, 256, AT_SMEM_FLOATS * (int)sizeof(float)>>>(qkv, ab, attn);
    }

    // 5. out-proj + residual(hs)
    dim3 gP(D_MODEL / 128, M_ROWS / 128);
    gemm_tf32<false><<<gP, 256>>>(attn, wo, bo, hs, res1, M_ROWS, D_MODEL, D_MODEL);

    // 6. LN3
    ln_kernel<<<M_ROWS, 256>>>(res1, g3, be3, ffin);

    // 7. FFN1 + exact GELU
    dim3 gF1(FFN_DIM / 128, M_ROWS / 128);
    gemm_tf32<true><<<gF1, 256>>>(ffin, w1, b1, nullptr, hbuf, M_ROWS, FFN_DIM, D_MODEL);

    // 8. FFN2 + residual(res1) -> out
    gemm_tf32<false><<<gP, 256>>>(hbuf, w2, b2, res1, out, M_ROWS, D_MODEL, FFN_DIM);
}

// round 4
// speedup vs baseline: 3.2390x; 1.1709x over previous
#include <cuda_runtime.h>
#include <cuda_bf16.h>
#include <math.h>

#define D_MODEL 768
#define N_HEADS 12
#define HEAD_DIM 64
#define FFN_DIM 3072
#define T_TOK 2048
#define BATCH 2
#define M_ROWS (BATCH * T_TOK)   // 4096
#define QKV_N 2304               // 3 * D_MODEL

// -------------------- scratch ---------------------------------------------
__device__ float g_ni[M_ROWS * D_MODEL];
__device__ float g_qkv[M_ROWS * QKV_N];
__device__ float g_wqkv[D_MODEL * QKV_N];
__device__ float g_bqkv[QKV_N];
__device__ float g_attn[M_ROWS * D_MODEL];
__device__ float g_res1[M_ROWS * D_MODEL];
__device__ float g_ffin[M_ROWS * D_MODEL];
__device__ float g_h[M_ROWS * FFN_DIM];
__device__ float g_trig[T_TOK * 16 * 2];   // cos, sin per (t, band)

// -------------------- async copy helpers ----------------------------------
__device__ __forceinline__ void cp16(void* smem_dst, const void* gptr) {
    unsigned a = (unsigned)__cvta_generic_to_shared(smem_dst);
    asm volatile("cp.async.ca.shared.global [%0], [%1], 16;" :: "r"(a), "l"(gptr));
}
__device__ __forceinline__ void cp_commit() { asm volatile("cp.async.commit_group;"); }
template <int NN>
__device__ __forceinline__ void cp_wait() { asm volatile("cp.async.wait_group %0;" :: "n"(NN)); }

__device__ __forceinline__ void mma_tf32(float* c, const unsigned* a, const unsigned* b) {
    asm volatile(
        "mma.sync.aligned.m16n8k8.row.col.f32.tf32.tf32.f32 "
        "{%0,%1,%2,%3}, {%4,%5,%6,%7}, {%8,%9}, {%0,%1,%2,%3};"
        : "+f"(c[0]), "+f"(c[1]), "+f"(c[2]), "+f"(c[3])
        : "r"(a[0]), "r"(a[1]), "r"(a[2]), "r"(a[3]), "r"(b[0]), "r"(b[1]));
}

// -------------------- block reduction -------------------------------------
__device__ __forceinline__ float block_sum_256(float val) {
    __shared__ float red[8];
    int lane = threadIdx.x & 31, w = threadIdx.x >> 5;
#pragma unroll
    for (int o = 16; o; o >>= 1) val += __shfl_xor_sync(0xffffffffu, val, o);
    if (lane == 0) red[w] = val;
    __syncthreads();
    if (w == 0) {
        float t = (lane < 8) ? red[lane] : 0.f;
#pragma unroll
        for (int o = 4; o; o >>= 1) t += __shfl_xor_sync(0xffffffffu, t, o);
        if (lane == 0) red[0] = t;
    }
    __syncthreads();
    float r = red[0];
    __syncthreads();
    return r;
}

// -------------------- LayerNorm -------------------------------------------
__global__ void ln_kernel(const float* __restrict__ x, const float* __restrict__ g,
                          const float* __restrict__ bta, float* __restrict__ y) {
    size_t row = blockIdx.x;
    int tid = threadIdx.x;
    const float* xr = x + row * D_MODEL;
    float v0 = xr[tid], v1 = xr[tid + 256], v2 = xr[tid + 512];
    float mu = block_sum_256(v0 + v1 + v2) * (1.f / 768.f);
    float d0 = v0 - mu, d1 = v1 - mu, d2 = v2 - mu;
    float var = block_sum_256(d0 * d0 + d1 * d1 + d2 * d2) * (1.f / 768.f);
    float rs = rsqrtf(var + 1e-5f);
    float* yr = y + row * D_MODEL;
    yr[tid]       = d0 * rs * g[tid]       + bta[tid];
    yr[tid + 256] = d1 * rs * g[tid + 256] + bta[tid + 256];
    yr[tid + 512] = d2 * rs * g[tid + 512] + bta[tid + 512];
}

// -------------------- QKV weight/bias concat (q scaled by 0.125) ----------
__global__ void concat_qkv(const float* __restrict__ wq, const float* __restrict__ wk,
                           const float* __restrict__ wv, const float* __restrict__ bq,
                           const float* __restrict__ bk, const float* __restrict__ bv,
                           float* __restrict__ W, float* __restrict__ Bo) {
    int idx = blockIdx.x * 256 + threadIdx.x;           // float4 index
    const int total = D_MODEL * QKV_N / 4;
    if (idx < total) {
        int e = idx * 4;
        int k = e / QKV_N, j = e % QKV_N;
        float4 v;
        if (j < 768) {
            v = *(const float4*)(wq + (size_t)k * 768 + j);
            v.x *= 0.125f; v.y *= 0.125f; v.z *= 0.125f; v.w *= 0.125f;
        } else if (j < 1536) {
            v = *(const float4*)(wk + (size_t)k * 768 + (j - 768));
        } else {
            v = *(const float4*)(wv + (size_t)k * 768 + (j - 1536));
        }
        *(float4*)(W + e) = v;
    }
    if (idx < QKV_N / 4) {
        int j = idx * 4;
        float4 v;
        if (j < 768) {
            v = *(const float4*)(bq + j);
            v.x *= 0.125f; v.y *= 0.125f; v.z *= 0.125f; v.w *= 0.125f;
        } else if (j < 1536) {
            v = *(const float4*)(bk + (j - 768));
        } else {
            v = *(const float4*)(bv + (j - 1536));
        }
        *(float4*)(Bo + j) = v;
    }
}

// -------------------- trig table: 2048 x 16 (double precision once) -------
__global__ void trig_kernel(float* __restrict__ trig) {
    int idx = blockIdx.x * 256 + threadIdx.x;
    if (idx >= T_TOK * 16) return;
    int t = idx >> 4, i = idx & 15;
    double ts = pow(10000.0, (double)i / 32.0);
    double ang = (double)t / ts;
    double sd, cd;
    sincos(ang, &sd, &cd);
    trig[idx * 2]     = (float)cd;
    trig[idx * 2 + 1] = (float)sd;
}

// -------------------- p-RoPE apply (table lookup) --------------------------
__global__ void rope_apply(float* __restrict__ qkv, const float* __restrict__ trig) {
    int idx = blockIdx.x * blockDim.x + threadIdx.x;
    const int total = BATCH * T_TOK * N_HEADS * 16;
    if (idx >= total) return;
    int i = idx & 15;
    int h = (idx >> 4) % N_HEADS;
    int t = (idx / (16 * N_HEADS)) % T_TOK;
    int b = idx / (16 * N_HEADS * T_TOK);
    size_t base = ((size_t)(b * T_TOK + t)) * QKV_N + h * HEAD_DIM + i;
    float cf = trig[(t * 16 + i) * 2];
    float sf = trig[(t * 16 + i) * 2 + 1];
    float x1 = qkv[base], x2 = qkv[base + 32];          // q
    qkv[base]      = x1 * cf - x2 * sf;
    qkv[base + 32] = x2 * cf + x1 * sf;
    x1 = qkv[base + 768]; x2 = qkv[base + 800];          // k
    qkv[base + 768] = x1 * cf - x2 * sf;
    qkv[base + 800] = x2 * cf + x1 * sf;
}

// -------------------- tf32 GEMM: cp.async double-buffered ------------------
#define AS_STRIDE 20
#define BS_STRIDE 136
template <bool GELU>
__global__ __launch_bounds__(256, 2)
void gemm_tf32(const float* __restrict__ A, const float* __restrict__ Bm,
               const float* __restrict__ bias, const float* __restrict__ res,
               float* __restrict__ C, int M, int N, int K) {
    __shared__ unsigned As[2][128 * AS_STRIDE];
    __shared__ unsigned Bs[2][16 * BS_STRIDE];
    int tid = threadIdx.x;
    int wid = tid >> 5, lane = tid & 31;
    int g = lane >> 2, tig = lane & 3;
    int wm = wid & 3, wn = wid >> 2;           // warp grid 4 x 2
    int brow = blockIdx.y * 128, bcol = blockIdx.x * 128;

    int ar = tid >> 2, ac = (tid & 3) * 4;
    int br = tid >> 5, bc = (tid & 31) * 4;
    const float* Ap = A + (size_t)(brow + ar) * K + ac;
    const float* Bp = Bm + (size_t)br * N + bcol + bc;

    int nIter = K >> 4;
    {
        cp16(&As[0][ar * AS_STRIDE + ac], Ap);
        cp16(&As[0][(ar + 64) * AS_STRIDE + ac], Ap + (size_t)64 * K);
        cp16(&Bs[0][br * BS_STRIDE + bc], Bp);
        cp16(&Bs[0][(br + 8) * BS_STRIDE + bc], Bp + (size_t)8 * N);
        cp_commit();
    }

    float acc[2][8][4];
#pragma unroll
    for (int i = 0; i < 2; i++)
#pragma unroll
        for (int j = 0; j < 8; j++)
#pragma unroll
            for (int r = 0; r < 4; r++) acc[i][j][r] = 0.f;

    for (int kt = 0; kt < nIter; ++kt) {
        int cur = kt & 1;
        if (kt + 1 < nIter) {
            int nxt = cur ^ 1;
            const float* a0 = Ap + (kt + 1) * 16;
            const float* b0 = Bp + (size_t)(kt + 1) * 16 * N;
            cp16(&As[nxt][ar * AS_STRIDE + ac], a0);
            cp16(&As[nxt][(ar + 64) * AS_STRIDE + ac], a0 + (size_t)64 * K);
            cp16(&Bs[nxt][br * BS_STRIDE + bc], b0);
            cp16(&Bs[nxt][(br + 8) * BS_STRIDE + bc], b0 + (size_t)8 * N);
            cp_commit();
            cp_wait<1>();
        } else {
            cp_wait<0>();
        }
        __syncthreads();
#pragma unroll
        for (int ks = 0; ks < 16; ks += 8) {
            unsigned af[2][4];
#pragma unroll
            for (int mt = 0; mt < 2; mt++) {
                int r0 = wm * 32 + mt * 16 + g;
                af[mt][0] = As[cur][r0 * AS_STRIDE + ks + tig];
                af[mt][1] = As[cur][(r0 + 8) * AS_STRIDE + ks + tig];
                af[mt][2] = As[cur][r0 * AS_STRIDE + ks + tig + 4];
                af[mt][3] = As[cur][(r0 + 8) * AS_STRIDE + ks + tig + 4];
            }
#pragma unroll
            for (int nt = 0; nt < 8; nt++) {
                unsigned bf[2];
                int c0 = wn * 64 + nt * 8 + g;
                bf[0] = Bs[cur][(ks + tig) * BS_STRIDE + c0];
                bf[1] = Bs[cur][(ks + tig + 4) * BS_STRIDE + c0];
                mma_tf32(acc[0][nt], af[0], bf);
                mma_tf32(acc[1][nt], af[1], bf);
            }
        }
        __syncthreads();
    }

#pragma unroll
    for (int mt = 0; mt < 2; mt++) {
        int row0 = brow + wm * 32 + mt * 16 + g;
#pragma unroll
        for (int nt = 0; nt < 8; nt++) {
            int col = bcol + wn * 64 + nt * 8 + tig * 2;
            float b0 = bias[col], b1 = bias[col + 1];
            float v00 = acc[mt][nt][0] + b0;
            float v01 = acc[mt][nt][1] + b1;
            float v10 = acc[mt][nt][2] + b0;
            float v11 = acc[mt][nt][3] + b1;
            if (GELU) {
                v00 *= normcdff(v00); v01 *= normcdff(v01);
                v10 *= normcdff(v10); v11 *= normcdff(v11);
            }
            if (res) {
                const float* r0p = res + (size_t)row0 * N + col;
                const float* r1p = res + (size_t)(row0 + 8) * N + col;
                v00 += r0p[0]; v01 += r0p[1];
                v10 += r1p[0]; v11 += r1p[1];
            }
            *(float2*)(C + (size_t)row0 * N + col) = make_float2(v00, v01);
            *(float2*)(C + (size_t)(row0 + 8) * N + col) = make_float2(v10, v11);
        }
    }
}

// -------------------- flash attention (tf32 mma, raw fp32 bits) -----------
#define QS_STRIDE 68
#define KS_STRIDE 76
#define VS_STRIDE 72
#define SC_STRIDE 68
#define AT_SMEM_FLOATS (64*QS_STRIDE + 64*KS_STRIDE + 64*VS_STRIDE + 64*SC_STRIDE + 192)

__global__ __launch_bounds__(256)
void attn_tf32(const float* __restrict__ QKV, const float* __restrict__ ab,
               float* __restrict__ O) {
    extern __shared__ float sm[];
    unsigned* Qs = (unsigned*)sm;
    unsigned* Ks = Qs + 64 * QS_STRIDE;
    unsigned* Vs = Ks + 64 * KS_STRIDE;
    float* Sc = (float*)(Vs + 64 * VS_STRIDE);
    float* mrow = Sc + 64 * SC_STRIDE;
    float* lrow = mrow + 64;
    float* srow = lrow + 64;
    unsigned* Scu = (unsigned*)Sc;

    int tid = threadIdx.x;
    int wid = tid >> 5, lane = tid & 31;
    int g = lane >> 2, tig = lane & 3;
    int m0 = (wid >> 1) * 16;
    int n0b = (wid & 1) * 32;

    int qb = blockIdx.x * 64;
    int h = blockIdx.y, b = blockIdx.z;
    size_t bh = (size_t)b * T_TOK * QKV_N + h * HEAD_DIM;
    const float* qp = QKV + bh;
    const float* kp = QKV + bh + 768;
    const float* vp = QKV + bh + 1536;

#pragma unroll
    for (int it = 0; it < 4; it++) {
        int idx = tid + it * 256;
        int r = idx >> 4, c4 = (idx & 15) * 4;
        cp16(&Qs[r * QS_STRIDE + c4], qp + (size_t)(qb + r) * QKV_N + c4);
    }
    cp_commit();
    if (tid < 64) { mrow[tid] = -1e30f; lrow[tid] = 0.f; }

    float o[4][4];
#pragma unroll
    for (int i = 0; i < 4; i++)
#pragma unroll
        for (int j = 0; j < 4; j++) o[i][j] = 0.f;

    float bias0 = ab[h * 2 + 0], bias1 = ab[h * 2 + 1];
    int qvar = qb >> 7;

    for (int kt = 0; kt < 32; kt++) {
        int kb = kt * 64;
#pragma unroll
        for (int it = 0; it < 4; it++) {
            int idx = tid + it * 256;
            int r = idx >> 4, c4 = (idx & 15) * 4;
            cp16(&Ks[r * KS_STRIDE + c4], kp + (size_t)(kb + r) * QKV_N + c4);
            cp16(&Vs[r * VS_STRIDE + c4], vp + (size_t)(kb + r) * QKV_N + c4);
        }
        cp_commit();
        cp_wait<0>();
        __syncthreads();

        // ---- S = Q @ K^T ----
        float s[4][4];
#pragma unroll
        for (int i = 0; i < 4; i++)
#pragma unroll
            for (int j = 0; j < 4; j++) s[i][j] = 0.f;
#pragma unroll
        for (int ks = 0; ks < 64; ks += 8) {
            unsigned af[4];
            af[0] = Qs[(m0 + g) * QS_STRIDE + ks + tig];
            af[1] = Qs[(m0 + g + 8) * QS_STRIDE + ks + tig];
            af[2] = Qs[(m0 + g) * QS_STRIDE + ks + tig + 4];
            af[3] = Qs[(m0 + g + 8) * QS_STRIDE + ks + tig + 4];
#pragma unroll
            for (int nt = 0; nt < 4; nt++) {
                unsigned bf[2];
                int c0 = n0b + nt * 8 + g;
                bf[0] = Ks[c0 * KS_STRIDE + ks + tig];
                bf[1] = Ks[c0 * KS_STRIDE + ks + tig + 4];
                mma_tf32(s[nt], af, bf);
            }
        }
        float bias = ((kb >> 7) == qvar) ? bias0 : bias1;
#pragma unroll
        for (int nt = 0; nt < 4; nt++) {
            int col = n0b + nt * 8 + tig * 2;
            Sc[(m0 + g) * SC_STRIDE + col]     = s[nt][0] + bias;
            Sc[(m0 + g) * SC_STRIDE + col + 1] = s[nt][1] + bias;
            Sc[(m0 + g + 8) * SC_STRIDE + col]     = s[nt][2] + bias;
            Sc[(m0 + g + 8) * SC_STRIDE + col + 1] = s[nt][3] + bias;
        }
        __syncthreads();

        // ---- online softmax: 4 threads per row, 16 cols each ----
        {
            int r = tid >> 2, seg = tid & 3;
            float* sr = &Sc[r * SC_STRIDE + seg * 16];
            float mo = mrow[r];
            float mx = -1e30f;
#pragma unroll
            for (int j = 0; j < 16; j++) mx = fmaxf(mx, sr[j]);
            mx = fmaxf(mx, __shfl_xor_sync(0xffffffffu, mx, 1));
            mx = fmaxf(mx, __shfl_xor_sync(0xffffffffu, mx, 2));
            mx = fmaxf(mx, mo);
            float sum = 0.f;
#pragma unroll
            for (int j = 0; j < 16; j++) {
                float p = __expf(sr[j] - mx);
                sr[j] = p;
                sum += p;
            }
            sum += __shfl_xor_sync(0xffffffffu, sum, 1);
            sum += __shfl_xor_sync(0xffffffffu, sum, 2);
            if (seg == 0) {
                float scl = __expf(mo - mx);
                mrow[r] = mx;
                lrow[r] = lrow[r] * scl + sum;
                srow[r] = scl;
            }
        }
        __syncthreads();

        // ---- rescale + O += P @ V ----
        float scl0 = srow[m0 + g], scl1 = srow[m0 + g + 8];
#pragma unroll
        for (int nt = 0; nt < 4; nt++) {
            o[nt][0] *= scl0; o[nt][1] *= scl0;
            o[nt][2] *= scl1; o[nt][3] *= scl1;
        }
#pragma unroll
        for (int ks = 0; ks < 64; ks += 8) {
            unsigned af[4];
            af[0] = Scu[(m0 + g) * SC_STRIDE + ks + tig];
            af[1] = Scu[(m0 + g + 8) * SC_STRIDE + ks + tig];
            af[2] = Scu[(m0 + g) * SC_STRIDE + ks + tig + 4];
            af[3] = Scu[(m0 + g + 8) * SC_STRIDE + ks + tig + 4];
#pragma unroll
            for (int nt = 0; nt < 4; nt++) {
                unsigned bf[2];
                int c0 = n0b + nt * 8 + g;
                bf[0] = Vs[(ks + tig) * VS_STRIDE + c0];
                bf[1] = Vs[(ks + tig + 4) * VS_STRIDE + c0];
                mma_tf32(o[nt], af, bf);
            }
        }
        __syncthreads();
    }

    float inv0 = 1.f / lrow[m0 + g], inv1 = 1.f / lrow[m0 + g + 8];
    int row0 = qb + m0 + g;
#pragma unroll
    for (int nt = 0; nt < 4; nt++) {
        int col = n0b + nt * 8 + tig * 2;
        float* o0 = O + (size_t)(b * T_TOK + row0) * D_MODEL + h * HEAD_DIM + col;
        float* o1 = O + (size_t)(b * T_TOK + row0 + 8) * D_MODEL + h * HEAD_DIM + col;
        *(float2*)o0 = make_float2(o[nt][0] * inv0, o[nt][1] * inv0);
        *(float2*)o1 = make_float2(o[nt][2] * inv1, o[nt][3] * inv1);
    }
}

// -------------------- launch ----------------------------------------------
extern "C" void kernel_launch(void* const* d_in, const int* in_sizes, int n_in,
                              void* d_out, int out_size) {
    const float* hs  = (const float*)d_in[0];
    const float* wq  = (const float*)d_in[1];
    const float* bq  = (const float*)d_in[2];
    const float* wk  = (const float*)d_in[3];
    const float* bk  = (const float*)d_in[4];
    const float* wv  = (const float*)d_in[5];
    const float* bv  = (const float*)d_in[6];
    const float* wo  = (const float*)d_in[7];
    const float* bo  = (const float*)d_in[8];
    const float* ab  = (const float*)d_in[9];
    const float* g1  = (const float*)d_in[10];
    const float* be1 = (const float*)d_in[11];
    const float* g3  = (const float*)d_in[12];
    const float* be3 = (const float*)d_in[13];
    const float* w1  = (const float*)d_in[14];
    const float* b1  = (const float*)d_in[15];
    const float* w2  = (const float*)d_in[16];
    const float* b2  = (const float*)d_in[17];
    float* out = (float*)d_out;

    float *ni, *qkv, *wqkv, *bqkv, *attn, *res1, *ffin, *hbuf, *trig;
    cudaGetSymbolAddress((void**)&ni,   g_ni);
    cudaGetSymbolAddress((void**)&qkv,  g_qkv);
    cudaGetSymbolAddress((void**)&wqkv, g_wqkv);
    cudaGetSymbolAddress((void**)&bqkv, g_bqkv);
    cudaGetSymbolAddress((void**)&attn, g_attn);
    cudaGetSymbolAddress((void**)&res1, g_res1);
    cudaGetSymbolAddress((void**)&ffin, g_ffin);
    cudaGetSymbolAddress((void**)&hbuf, g_h);
    cudaGetSymbolAddress((void**)&trig, g_trig);

    static bool attr_set = false;
    if (!attr_set) {
        cudaFuncSetAttribute(attn_tf32, cudaFuncAttributeMaxDynamicSharedMemorySize,
                             AT_SMEM_FLOATS * (int)sizeof(float));
        attr_set = true;
    }

    // 0. trig table + QKV weight concat
    trig_kernel<<<(T_TOK * 16 + 255) / 256, 256>>>(trig);
    concat_qkv<<<(D_MODEL * QKV_N / 4 + 255) / 256, 256>>>(wq, wk, wv, bq, bk, bv, wqkv, bqkv);

    // 1. LN1
    ln_kernel<<<M_ROWS, 256>>>(hs, g1, be1, ni);

    // 2. fused QKV projection
    dim3 gQKV(QKV_N / 128, M_ROWS / 128);
    gemm_tf32<false><<<gQKV, 256>>>(ni, wqkv, bqkv, nullptr, qkv, M_ROWS, QKV_N, D_MODEL);

    // 3. RoPE (table lookup)
    {
        int total = BATCH * T_TOK * N_HEADS * 16;
        rope_apply<<<(total + 255) / 256, 256>>>(qkv, trig);
    }

    // 4. attention
    {
        dim3 ga(T_TOK / 64, N_HEADS, BATCH);
        attn_tf32<<<ga, 256, AT_SMEM_FLOATS * (int)sizeof(float)>>>(qkv, ab, attn);
    }

    // 5. out-proj + residual(hs)
    dim3 gP(D_MODEL / 128, M_ROWS / 128);
    gemm_tf32<false><<<gP, 256>>>(attn, wo, bo, hs, res1, M_ROWS, D_MODEL, D_MODEL);

    // 6. LN3
    ln_kernel<<<M_ROWS, 256>>>(res1, g3, be3, ffin);

    // 7. FFN1 + exact GELU
    dim3 gF1(FFN_DIM / 128, M_ROWS / 128);
    gemm_tf32<true><<<gF1, 256>>>(ffin, w1, b1, nullptr, hbuf, M_ROWS, FFN_DIM, D_MODEL);

    // 8. FFN2 + residual(res1) -> out
    gemm_tf32<false><<<gP, 256>>>(hbuf, w2, b2, res1, out, M_ROWS, D_MODEL, FFN_DIM);
}